// round 5
// baseline (speedup 1.0000x reference)
#include <cuda_runtime.h>
#include <math.h>

// Problem constants
#define B_  4
#define C_  128
#define H_B 512
#define W_B 512
#define H_C 64
#define W_C 2048

// Precomputed per-column sampling data (allocation-free scratch)
__device__ int4   g_xy[W_C];   // x0c, y0c, x1c, y1c (clipped to [0,511])
__device__ float4 g_w[W_C];    // w00, w10, w01, w11 (validity folded in)

__global__ void precompute_kernel() {
    int w = blockIdx.x * blockDim.x + threadIdx.x;
    if (w >= W_C) return;

    const double PI = 3.14159265358979323846;
    double phi = -PI + (double)w * (2.0 * PI / (double)(W_C - 1));
    double xg = 50.0 * cos(phi);
    double yg = 50.0 * sin(phi);
    // x = (xg - XMIN)/(XMAX-XMIN)*(W_B-1),  y = (YMAX - yg)/(YMAX-YMIN)*(H_B-1)
    double x = (xg + 50.0) * (1.0 / 100.0) * (double)(W_B - 1);
    double y = (50.0 - yg) * (1.0 / 100.0) * (double)(H_B - 1);

    double fx0 = floor(x), fy0 = floor(y);
    int x0 = (int)fx0, y0 = (int)fy0;
    int x1 = x0 + 1,  y1 = y0 + 1;
    double wx1 = x - fx0, wx0 = 1.0 - wx1;
    double wy1 = y - fy0, wy0 = 1.0 - wy1;

    bool vx0 = (x0 >= 0) && (x0 < W_B);
    bool vx1 = (x1 >= 0) && (x1 < W_B);
    bool vy0 = (y0 >= 0) && (y0 < H_B);
    bool vy1 = (y1 >= 0) && (y1 < H_B);

    int x0c = min(max(x0, 0), W_B - 1);
    int x1c = min(max(x1, 0), W_B - 1);
    int y0c = min(max(y0, 0), H_B - 1);
    int y1c = min(max(y1, 0), H_B - 1);

    float w00 = (float)(wx0 * wy0) * (vx0 && vy0 ? 1.0f : 0.0f);
    float w10 = (float)(wx1 * wy0) * (vx1 && vy0 ? 1.0f : 0.0f);
    float w01 = (float)(wx0 * wy1) * (vx0 && vy1 ? 1.0f : 0.0f);
    float w11 = (float)(wx1 * wy1) * (vx1 && vy1 ? 1.0f : 0.0f);

    g_xy[w] = make_int4(x0c, y0c, x1c, y1c);
    g_w[w]  = make_float4(w00, w10, w01, w11);
}

// One thread per (b*c, w-group-of-4): compute 4 column values, broadcast to 64 rows.
__global__ __launch_bounds__(256) void bev2cyl_kernel(const float* __restrict__ bev,
                                                      float* __restrict__ out) {
    int tid = blockIdx.x * blockDim.x + threadIdx.x;   // 0 .. B_*C_*(W_C/4)-1
    const int WG = W_C / 4;                            // 512
    int w4 = tid & (WG - 1);
    int bc = tid >> 9;                                 // tid / 512

    const float* __restrict__ plane = bev + (size_t)bc * (H_B * W_B);

    float4 val;
    float v[4];
#pragma unroll
    for (int j = 0; j < 4; j++) {
        int w = w4 * 4 + j;
        int4   xy = g_xy[w];
        float4 ww = g_w[w];
        float p00 = __ldg(plane + xy.y * W_B + xy.x);
        float p10 = __ldg(plane + xy.y * W_B + xy.z);
        float p01 = __ldg(plane + xy.w * W_B + xy.x);
        float p11 = __ldg(plane + xy.w * W_B + xy.z);
        v[j] = p00 * ww.x + p10 * ww.y + p01 * ww.z + p11 * ww.w;
    }
    val.x = v[0]; val.y = v[1]; val.z = v[2]; val.w = v[3];

    // out[bc][h][w] as float4 rows: bc stride = H_C * W_C/4 = 64*512
    float4* __restrict__ out4 = (float4*)out;
    size_t base = (size_t)bc * (H_C * WG) + w4;
#pragma unroll 8
    for (int h = 0; h < H_C; h++) {
        out4[base + (size_t)h * WG] = val;
    }
}

extern "C" void kernel_launch(void* const* d_in, const int* in_sizes, int n_in,
                              void* d_out, int out_size) {
    const float* bev = (const float*)d_in[0];
    float* out = (float*)d_out;

    precompute_kernel<<<(W_C + 255) / 256, 256>>>();

    int total_threads = B_ * C_ * (W_C / 4);          // 262144
    bev2cyl_kernel<<<total_threads / 256, 256>>>(bev, out);
}

// round 6
// speedup vs baseline: 1.2532x; 1.2532x over previous
#include <cuda_runtime.h>
#include <math.h>

// Problem constants
#define B_  4
#define C_  128
#define H_B 512
#define W_B 512
#define H_C 64
#define W_C 2048
#define BC_ (B_ * C_)          // 512 planes

// Scratch: one bilinear-sampled column value per (bc, w).  4 MB — L2-resident.
__device__ float g_col[BC_ * W_C];

// ---------------------------------------------------------------------------
// Phase 1: gather.  One thread per (bc, w).  All scattered reads live here,
// isolated from the big write stream.  Sampling params computed inline in
// float (sincosf accurate to ~1e-7 abs; bilinear is continuous across floor
// boundaries so the error stays ~1e-4, well under the 1e-3 gate).
// ---------------------------------------------------------------------------
__global__ __launch_bounds__(256) void gather_kernel(const float* __restrict__ bev) {
    int tid = blockIdx.x * blockDim.x + threadIdx.x;   // 0 .. BC_*W_C-1
    int w  = tid & (W_C - 1);
    int bc = tid >> 11;                                // / 2048

    // phi = linspace(-pi, pi, 2048)[w]
    const float STEP = (float)(6.283185307179586 / 2047.0);
    float phi = fmaf((float)w, STEP, -3.14159265358979f);
    float s, c;
    sincosf(phi, &s, &c);
    float xg = 50.0f * c;
    float yg = 50.0f * s;
    float x = (xg + 50.0f) * (511.0f / 100.0f);
    float y = (50.0f - yg) * (511.0f / 100.0f);

    float fx0 = floorf(x), fy0 = floorf(y);
    int x0 = (int)fx0, y0 = (int)fy0;
    int x1 = x0 + 1,  y1 = y0 + 1;
    float wx1 = x - fx0, wx0 = 1.0f - wx1;
    float wy1 = y - fy0, wy0 = 1.0f - wy1;

    bool vx0 = (x0 >= 0) && (x0 < W_B);
    bool vx1 = (x1 >= 0) && (x1 < W_B);
    bool vy0 = (y0 >= 0) && (y0 < H_B);
    bool vy1 = (y1 >= 0) && (y1 < H_B);

    int x0c = min(max(x0, 0), W_B - 1);
    int x1c = min(max(x1, 0), W_B - 1);
    int y0c = min(max(y0, 0), H_B - 1);
    int y1c = min(max(y1, 0), H_B - 1);

    float w00 = (vx0 && vy0) ? wx0 * wy0 : 0.0f;
    float w10 = (vx1 && vy0) ? wx1 * wy0 : 0.0f;
    float w01 = (vx0 && vy1) ? wx0 * wy1 : 0.0f;
    float w11 = (vx1 && vy1) ? wx1 * wy1 : 0.0f;

    const float* __restrict__ plane = bev + (size_t)bc * (H_B * W_B);
    float p00 = __ldg(plane + y0c * W_B + x0c);
    float p10 = __ldg(plane + y0c * W_B + x1c);
    float p01 = __ldg(plane + y1c * W_B + x0c);
    float p11 = __ldg(plane + y1c * W_B + x1c);

    g_col[tid] = p00 * w00 + p10 * w10 + p01 * w01 + p11 * w11;
}

// ---------------------------------------------------------------------------
// Phase 2: broadcast.  Pure streaming: read col (L2-hot, 4 MB), write 256 MB
// with evict-first float4 stores.  One thread per (bc, w-group-of-4).
// ---------------------------------------------------------------------------
__global__ __launch_bounds__(256) void broadcast_kernel(float* __restrict__ out) {
    int tid = blockIdx.x * blockDim.x + threadIdx.x;   // 0 .. BC_*(W_C/4)-1
    const int WG = W_C / 4;                            // 512
    int w4 = tid & (WG - 1);
    int bc = tid >> 9;

    const float4* __restrict__ col4 = (const float4*)g_col;
    float4 val = __ldg(col4 + (size_t)bc * WG + w4);

    float4* __restrict__ out4 = (float4*)out;
    size_t base = (size_t)bc * (H_C * WG) + w4;
#pragma unroll 16
    for (int h = 0; h < H_C; h++) {
        __stcs(out4 + base + (size_t)h * WG, val);
    }
}

extern "C" void kernel_launch(void* const* d_in, const int* in_sizes, int n_in,
                              void* d_out, int out_size) {
    const float* bev = (const float*)d_in[0];
    float* out = (float*)d_out;

    gather_kernel<<<(BC_ * W_C) / 256, 256>>>(bev);            // 4096 blocks
    broadcast_kernel<<<(BC_ * (W_C / 4)) / 256, 256>>>(out);   // 1024 blocks
}

// round 9
// speedup vs baseline: 1.2988x; 1.0364x over previous
#include <cuda_runtime.h>
#include <math.h>

// Problem constants
#define B_  4
#define C_  128
#define H_B 512
#define W_B 512
#define H_C 64
#define W_C 2048
#define BC_ (B_ * C_)          // 512 planes

// One CTA per (bc, half): 256 threads.
// Phase A: cooperative gather of 1024 col values into SMEM.
// Phase B: pure streaming broadcast (64 rows x 1024 floats) with evict-first stores.
__global__ __launch_bounds__(256) void bev2cyl_fused(const float* __restrict__ bev,
                                                     float* __restrict__ out) {
    __shared__ float s_col[1024];

    const int t     = threadIdx.x;
    const int bc    = blockIdx.x >> 1;          // 0..511
    const int half  = blockIdx.x & 1;           // 0 or 1
    const int wbase = half << 10;               // 0 or 1024

    const float* __restrict__ plane = bev + (size_t)bc * (H_B * W_B);

    // ---- Phase A: gather 4 col values per thread ----
    const float STEP = (float)(6.283185307179586 / 2047.0);
#pragma unroll
    for (int k = 0; k < 4; k++) {
        int wi = k * 256 + t;                   // 0..1023 within half
        int w  = wbase + wi;                    // global column

        float phi = fmaf((float)w, STEP, -3.14159265358979f);
        float s, c;
        sincosf(phi, &s, &c);
        float x = (50.0f * c + 50.0f) * (511.0f / 100.0f);
        float y = (50.0f - 50.0f * s) * (511.0f / 100.0f);

        float fx0 = floorf(x), fy0 = floorf(y);
        int x0 = (int)fx0, y0 = (int)fy0;
        int x1 = x0 + 1,  y1 = y0 + 1;
        float wx1 = x - fx0, wx0 = 1.0f - wx1;
        float wy1 = y - fy0, wy0 = 1.0f - wy1;

        bool vx0 = (x0 >= 0) && (x0 < W_B);
        bool vx1 = (x1 >= 0) && (x1 < W_B);
        bool vy0 = (y0 >= 0) && (y0 < H_B);
        bool vy1 = (y1 >= 0) && (y1 < H_B);

        int x0c = min(max(x0, 0), W_B - 1);
        int x1c = min(max(x1, 0), W_B - 1);
        int y0c = min(max(y0, 0), H_B - 1);
        int y1c = min(max(y1, 0), H_B - 1);

        float w00 = (vx0 && vy0) ? wx0 * wy0 : 0.0f;
        float w10 = (vx1 && vy0) ? wx1 * wy0 : 0.0f;
        float w01 = (vx0 && vy1) ? wx0 * wy1 : 0.0f;
        float w11 = (vx1 && vy1) ? wx1 * wy1 : 0.0f;

        float p00 = __ldg(plane + y0c * W_B + x0c);
        float p10 = __ldg(plane + y0c * W_B + x1c);
        float p01 = __ldg(plane + y1c * W_B + x0c);
        float p11 = __ldg(plane + y1c * W_B + x1c);

        s_col[wi] = p00 * w00 + p10 * w10 + p01 * w01 + p11 * w11;
    }
    __syncthreads();

    // ---- Phase B: broadcast 64 rows ----
    const float4* __restrict__ s4 = (const float4*)s_col;
    float4 val = s4[t];                          // thread's 4 columns, cached in regs

    // out[bc][h][wbase + 4t .. +3] as float4:
    // index = bc*(H_C*W_C/4) + h*(W_C/4) + (wbase>>2) + t
    float4* __restrict__ out4 = (float4*)out;
    size_t base = (size_t)bc * (H_C * (W_C / 4)) + (wbase >> 2) + t;
#pragma unroll 16
    for (int h = 0; h < H_C; h++) {
        __stcs(out4 + base + (size_t)h * (W_C / 4), val);
    }
}

extern "C" void kernel_launch(void* const* d_in, const int* in_sizes, int n_in,
                              void* d_out, int out_size) {
    const float* bev = (const float*)d_in[0];
    float* out = (float*)d_out;

    bev2cyl_fused<<<BC_ * 2, 256>>>(bev, out);   // 1024 CTAs
}

// round 10
// speedup vs baseline: 1.3125x; 1.0106x over previous
#include <cuda_runtime.h>
#include <math.h>

// Problem constants
#define B_  4
#define C_  128
#define H_B 512
#define W_B 512
#define H_C 64
#define W_C 2048
#define BC_ (B_ * C_)          // 512 planes

#define WCH 256                // w columns per CTA
#define NCHUNK (W_C / WCH)     // 8 chunks per plane
#define QPW (WCH / 4)          // 64 float4 quads per row segment

// One CTA per (bc, w-chunk).  256 threads.
// Phase A: each thread gathers ONE column value (1 sincosf + 4 LDG) -> SMEM.
// Phase B: 64 rows x 256 floats, each thread stores 16 float4 (evict-first).
// Grid = 4096 CTAs (~3.5 waves): later waves' gathers hide under earlier
// waves' store streams; only the first wave's small gather bubble is exposed.
__global__ __launch_bounds__(256) void bev2cyl_fused(const float* __restrict__ bev,
                                                     float* __restrict__ out) {
    __shared__ float s_col[WCH];

    const int t     = threadIdx.x;
    const int bc    = blockIdx.x >> 3;            // / NCHUNK
    const int chunk = blockIdx.x & (NCHUNK - 1);
    const int wbase = chunk * WCH;

    const float* __restrict__ plane = bev + (size_t)bc * (H_B * W_B);

    // ---- Phase A: one column per thread ----
    {
        int w = wbase + t;

        const float STEP = (float)(6.283185307179586 / 2047.0);
        float phi = fmaf((float)w, STEP, -3.14159265358979f);
        float s, c;
        sincosf(phi, &s, &c);
        float x = (50.0f * c + 50.0f) * (511.0f / 100.0f);
        float y = (50.0f - 50.0f * s) * (511.0f / 100.0f);

        float fx0 = floorf(x), fy0 = floorf(y);
        int x0 = (int)fx0, y0 = (int)fy0;
        int x1 = x0 + 1,  y1 = y0 + 1;
        float wx1 = x - fx0, wx0 = 1.0f - wx1;
        float wy1 = y - fy0, wy0 = 1.0f - wy1;

        bool vx0 = (x0 >= 0) && (x0 < W_B);
        bool vx1 = (x1 >= 0) && (x1 < W_B);
        bool vy0 = (y0 >= 0) && (y0 < H_B);
        bool vy1 = (y1 >= 0) && (y1 < H_B);

        int x0c = min(max(x0, 0), W_B - 1);
        int x1c = min(max(x1, 0), W_B - 1);
        int y0c = min(max(y0, 0), H_B - 1);
        int y1c = min(max(y1, 0), H_B - 1);

        float w00 = (vx0 && vy0) ? wx0 * wy0 : 0.0f;
        float w10 = (vx1 && vy0) ? wx1 * wy0 : 0.0f;
        float w01 = (vx0 && vy1) ? wx0 * wy1 : 0.0f;
        float w11 = (vx1 && vy1) ? wx1 * wy1 : 0.0f;

        float p00 = __ldg(plane + y0c * W_B + x0c);
        float p10 = __ldg(plane + y0c * W_B + x1c);
        float p01 = __ldg(plane + y1c * W_B + x0c);
        float p11 = __ldg(plane + y1c * W_B + x1c);

        s_col[t] = p00 * w00 + p10 * w10 + p01 * w01 + p11 * w11;
    }
    __syncthreads();

    // ---- Phase B: broadcast 64 rows of this 256-wide chunk ----
    const int quad = t & (QPW - 1);               // 0..63
    const int h0   = t >> 6;                      // 0..3
    const float4* __restrict__ s4 = (const float4*)s_col;
    float4 val = s4[quad];                        // broadcast read, no conflicts

    // out[bc][h][wbase + 4*quad ...]: full-row quad stride = W_C/4 = 512
    float4* __restrict__ out4 = (float4*)out;
    size_t base = (size_t)bc * (H_C * (W_C / 4)) + (size_t)(wbase >> 2) + quad;
#pragma unroll 16
    for (int i = 0; i < H_C / 4; i++) {
        int h = h0 + 4 * i;
        __stcs(out4 + base + (size_t)h * (W_C / 4), val);
    }
}

extern "C" void kernel_launch(void* const* d_in, const int* in_sizes, int n_in,
                              void* d_out, int out_size) {
    const float* bev = (const float*)d_in[0];
    float* out = (float*)d_out;

    bev2cyl_fused<<<BC_ * NCHUNK, 256>>>(bev, out);   // 4096 CTAs
}